// round 3
// baseline (speedup 1.0000x reference)
#include <cuda_runtime.h>
#include <math.h>

// ---------------- problem constants ----------------
#define NB   4
#define NT   1024
#define NC   1024
#define NH   16
#define NDH  64
#define NDL  32
#define NE   8
#define NDFF 4096
#define NTOK (NB*NT)     // 4096 tokens
#define NBH  (NB*NH)     // 64 (b,h) pairs

// output layout: [x | k_lat | v_lat | aux]
#define OFF_KL  ((size_t)NTOK*NC)
#define OFF_VL  (OFF_KL + (size_t)NTOK*NH*NDL)
#define OFF_AUX (OFF_VL + (size_t)NTOK*NH*NDL)

// ---------------- device scratch (no allocations allowed) ----------------
__device__ float g_h  [NTOK*NC];
__device__ float g_q  [NTOK*NC];
__device__ float g_k  [NBH*NT*NDH];
__device__ float g_v  [NBH*NT*NDH];
__device__ float g_y  [NTOK*NC];
__device__ float g_h2 [NTOK*NC];
__device__ float g_act[(size_t)NTOK*2*NDFF];
__device__ int   g_cnt[NE];
__device__ int   g_off[NE];
__device__ int   g_pos[NE];
__device__ int   g_topi[NTOK*2];
__device__ float g_topw[NTOK*2];
__device__ int   g_tok[NTOK*2];
__device__ float g_tw [NTOK*2];
__device__ float g_frac[NE];

__global__ void init_kernel() {
    int t = threadIdx.x;
    if (t < NE) { g_cnt[t] = 0; g_pos[t] = 0; g_frac[t] = 0.f; }
}

// ---------------- layernorm ----------------
__global__ void ln_kernel(const float* __restrict__ x, const float* __restrict__ w,
                          float* __restrict__ out) {
    int token = blockIdx.x;
    const float* xr = x + (size_t)token * NC;
    float s = 0.f, s2 = 0.f;
    for (int c = threadIdx.x; c < NC; c += 256) { float v = xr[c]; s += v; s2 += v*v; }
    #pragma unroll
    for (int o = 16; o; o >>= 1) {
        s  += __shfl_xor_sync(0xffffffffu, s,  o);
        s2 += __shfl_xor_sync(0xffffffffu, s2, o);
    }
    __shared__ float sw[8], sw2[8];
    __shared__ float s_mu, s_rstd;
    int warp = threadIdx.x >> 5, lane = threadIdx.x & 31;
    if (lane == 0) { sw[warp] = s; sw2[warp] = s2; }
    __syncthreads();
    if (threadIdx.x == 0) {
        float a = 0.f, b = 0.f;
        #pragma unroll
        for (int i = 0; i < 8; i++) { a += sw[i]; b += sw2[i]; }
        float mu  = a * (1.f/NC);
        float var = b * (1.f/NC) - mu*mu;
        s_mu = mu; s_rstd = rsqrtf(var + 1e-5f);
    }
    __syncthreads();
    float mu = s_mu, rstd = s_rstd;
    float* orow = out + (size_t)token * NC;
    for (int c = threadIdx.x; c < NC; c += 256)
        orow[c] = (xr[c] - mu) * rstd * w[c];
}

// ================= 128x128x8 double-buffered SGEMM, 8x8 microtile =========
// 256 threads. Fragment layout: rows {ty*4..+3, 64+ty*4..+3}, cols likewise
// (tx). All LDS are float4 and conflict-free; one __syncthreads per k-tile.

#define GEMM_PROLOGUE() \
    __shared__ __align__(16) float As[2][8][132]; \
    __shared__ __align__(16) float Bs[2][8][132]; \
    int tid = threadIdx.x; \
    int tx = tid & 15, ty = tid >> 4; \
    int arow = tid >> 1, ak = (tid & 1) * 4; \
    int bkr  = tid >> 5, bn = (tid & 31) * 4; \
    float acc[8][8]; \
    _Pragma("unroll") \
    for (int i = 0; i < 8; i++) \
        _Pragma("unroll") \
        for (int j = 0; j < 8; j++) acc[i][j] = 0.f;

#define GEMM_STORE_A(buf, a4) \
    As[buf][ak+0][arow] = a4.x; As[buf][ak+1][arow] = a4.y; \
    As[buf][ak+2][arow] = a4.z; As[buf][ak+3][arow] = a4.w;

#define GEMM_COMPUTE(cur) \
    _Pragma("unroll") \
    for (int kk = 0; kk < 8; kk++) { \
        float4 ar0 = *(const float4*)&As[cur][kk][ty*4]; \
        float4 ar1 = *(const float4*)&As[cur][kk][64 + ty*4]; \
        float4 br0 = *(const float4*)&Bs[cur][kk][tx*4]; \
        float4 br1 = *(const float4*)&Bs[cur][kk][64 + tx*4]; \
        float av[8] = {ar0.x, ar0.y, ar0.z, ar0.w, ar1.x, ar1.y, ar1.z, ar1.w}; \
        float bv[8] = {br0.x, br0.y, br0.z, br0.w, br1.x, br1.y, br1.z, br1.w}; \
        _Pragma("unroll") \
        for (int i = 0; i < 8; i++) \
            _Pragma("unroll") \
            for (int j = 0; j < 8; j++) acc[i][j] += av[i] * bv[j]; \
    }

// ---- plain: C[M,N] = A[M,K] @ B[K,N] (+resid). M,N multiples of 128 -------
__global__ void __launch_bounds__(256) gemm128(
    const float* __restrict__ A, const float* __restrict__ Bm,
    float* __restrict__ Cm, const float* __restrict__ resid, int N, int K)
{
    GEMM_PROLOGUE();
    int row0 = blockIdx.y * 128, col0 = blockIdx.x * 128;
    const float* Aptr = A  + (size_t)(row0 + arow) * K + ak;
    const float* Bptr = Bm + (size_t)bkr * N + col0 + bn;

    float4 a4 = *(const float4*)Aptr;
    float4 b4 = *(const float4*)Bptr;
    GEMM_STORE_A(0, a4);
    *(float4*)&Bs[0][bkr][bn] = b4;
    __syncthreads();

    int ntiles = K >> 3;
    for (int kt = 0; kt < ntiles; kt++) {
        int cur = kt & 1, nxt = cur ^ 1;
        if (kt + 1 < ntiles) {
            a4 = *(const float4*)(Aptr + (kt+1)*8);
            b4 = *(const float4*)(Bptr + (size_t)(kt+1)*8*N);
        }
        GEMM_COMPUTE(cur);
        if (kt + 1 < ntiles) {
            GEMM_STORE_A(nxt, a4);
            *(float4*)&Bs[nxt][bkr][bn] = b4;
            __syncthreads();
        }
    }
    #pragma unroll
    for (int ih = 0; ih < 2; ih++)
        #pragma unroll
        for (int i = 0; i < 4; i++) {
            int m = row0 + ih*64 + ty*4 + i;
            #pragma unroll
            for (int jh = 0; jh < 2; jh++) {
                size_t off = (size_t)m * N + col0 + jh*64 + tx*4;
                float4 r = make_float4(acc[ih*4+i][jh*4+0], acc[ih*4+i][jh*4+1],
                                       acc[ih*4+i][jh*4+2], acc[ih*4+i][jh*4+3]);
                if (resid) {
                    float4 rv = *(const float4*)(resid + off);
                    r.x += rv.x; r.y += rv.y; r.z += rv.z; r.w += rv.w;
                }
                *(float4*)(Cm + off) = r;
            }
        }
}

// ---- MoE GEMM1: act = gelu(h2[gather] @ fc_w[e]); grid (32, 32, 8) --------
__global__ void __launch_bounds__(256) moe_gemm1(const float* __restrict__ FC)
{
    int e = blockIdx.z;
    int Me = g_cnt[e]; if (Me == 0) return;
    int base = g_off[e];
    int row0 = blockIdx.y * 128; if (row0 >= Me) return;
    int col0 = blockIdx.x * 128;
    const float* Bm = FC + (size_t)e * NC * NDFF;

    GEMM_PROLOGUE();
    int ar_ = row0 + arow;
    int atok = (ar_ < Me) ? g_tok[base + ar_] : g_tok[base];
    const float* Aptr = g_h2 + (size_t)atok * NC + ak;
    const float* Bptr = Bm + (size_t)bkr * NDFF + col0 + bn;

    float4 a4 = *(const float4*)Aptr;
    float4 b4 = *(const float4*)Bptr;
    GEMM_STORE_A(0, a4);
    *(float4*)&Bs[0][bkr][bn] = b4;
    __syncthreads();

    const int ntiles = NC >> 3;   // 128
    for (int kt = 0; kt < ntiles; kt++) {
        int cur = kt & 1, nxt = cur ^ 1;
        if (kt + 1 < ntiles) {
            a4 = *(const float4*)(Aptr + (kt+1)*8);
            b4 = *(const float4*)(Bptr + (size_t)(kt+1)*8*NDFF);
        }
        GEMM_COMPUTE(cur);
        if (kt + 1 < ntiles) {
            GEMM_STORE_A(nxt, a4);
            *(float4*)&Bs[nxt][bkr][bn] = b4;
            __syncthreads();
        }
    }
    #pragma unroll
    for (int ih = 0; ih < 2; ih++)
        #pragma unroll
        for (int i = 0; i < 4; i++) {
            int r = row0 + ih*64 + ty*4 + i;
            if (r < Me) {
                float* orow = g_act + (size_t)(base + r) * NDFF + col0;
                #pragma unroll
                for (int jh = 0; jh < 2; jh++) {
                    #pragma unroll
                    for (int j = 0; j < 4; j++) {
                        float v = acc[ih*4+i][jh*4+j];
                        orow[jh*64 + tx*4 + j] =
                            0.5f * v * (1.f + erff(v * 0.70710678118654752f));
                    }
                }
            }
        }
}

// ---- MoE GEMM2: xout[tok] += w*(act @ proj_w[e]); grid (8, 32, 8) ---------
__global__ void __launch_bounds__(256) moe_gemm2(const float* __restrict__ PW,
                                                 float* __restrict__ xout)
{
    int e = blockIdx.z;
    int Me = g_cnt[e]; if (Me == 0) return;
    int base = g_off[e];
    int row0 = blockIdx.y * 128; if (row0 >= Me) return;
    int col0 = blockIdx.x * 128;
    const float* Bm = PW + (size_t)e * NDFF * NC;

    GEMM_PROLOGUE();
    int ar_ = row0 + arow;
    int aslot = base + ((ar_ < Me) ? ar_ : (Me - 1));
    const float* Aptr = g_act + (size_t)aslot * NDFF + ak;
    const float* Bptr = Bm + (size_t)bkr * NC + col0 + bn;

    float4 a4 = *(const float4*)Aptr;
    float4 b4 = *(const float4*)Bptr;
    GEMM_STORE_A(0, a4);
    *(float4*)&Bs[0][bkr][bn] = b4;
    __syncthreads();

    const int ntiles = NDFF >> 3;  // 512
    for (int kt = 0; kt < ntiles; kt++) {
        int cur = kt & 1, nxt = cur ^ 1;
        if (kt + 1 < ntiles) {
            a4 = *(const float4*)(Aptr + (kt+1)*8);
            b4 = *(const float4*)(Bptr + (size_t)(kt+1)*8*NC);
        }
        GEMM_COMPUTE(cur);
        if (kt + 1 < ntiles) {
            GEMM_STORE_A(nxt, a4);
            *(float4*)&Bs[nxt][bkr][bn] = b4;
            __syncthreads();
        }
    }
    #pragma unroll
    for (int ih = 0; ih < 2; ih++)
        #pragma unroll
        for (int i = 0; i < 4; i++) {
            int r = row0 + ih*64 + ty*4 + i;
            if (r < Me) {
                int tok = g_tok[base + r];
                float w = g_tw[base + r];
                size_t off = (size_t)tok * NC + col0 + tx*4;
                #pragma unroll
                for (int jh = 0; jh < 2; jh++)
                    #pragma unroll
                    for (int j = 0; j < 4; j++)
                        atomicAdd(&xout[off + jh*64 + j], w * acc[ih*4+i][jh*4+j]);
            }
        }
}

// ---------------- latent->head up-projection + RoPE ----------------
__global__ void uprope_kernel(const float* __restrict__ klat, const float* __restrict__ vlat,
                              const float* __restrict__ kup,  const float* __restrict__ vup,
                              float* __restrict__ qbuf)
{
    int token = blockIdx.x;
    int b = token >> 10, t = token & 1023;
    __shared__ float skl[NH*NDL], svl[NH*NDL];
    __shared__ float sku[NDL*NDH], svu[NDL*NDH];
    int tid = threadIdx.x;
    for (int e = tid; e < NH*NDL; e += 256) {
        skl[e] = klat[(size_t)token*NH*NDL + e];
        svl[e] = vlat[(size_t)token*NH*NDL + e];
    }
    for (int e = tid; e < NDL*NDH; e += 256) { sku[e] = kup[e]; svu[e] = vup[e]; }
    __syncthreads();

    for (int p = tid; p < NH*32; p += 256) {
        int h = p >> 5, i = p & 31;
        int d0 = 2*i, d1 = 2*i + 1;
        float k0 = 0.f, k1 = 0.f, v0 = 0.f, v1 = 0.f;
        #pragma unroll
        for (int l = 0; l < NDL; l++) {
            float kl = skl[h*NDL + l], vl = svl[h*NDL + l];
            k0 += kl * sku[l*NDH + d0]; k1 += kl * sku[l*NDH + d1];
            v0 += vl * svu[l*NDH + d0]; v1 += vl * svu[l*NDH + d1];
        }
        int j0 = (d0 < 32) ? d0 : d0 - 32;
        int j1 = (d1 < 32) ? d1 : d1 - 32;
        float a0 = (float)t * powf(10000.f, -(float)j0 * (1.f/32.f));
        float a1 = (float)t * powf(10000.f, -(float)j1 * (1.f/32.f));
        float c0 = cosf(a0), s0 = sinf(a0), c1 = cosf(a1), s1 = sinf(a1);

        size_t kidx = ((size_t)(b*NH + h) * NT + t) * NDH;
        g_k[kidx + d0] = k0*c0 - k1*s0;
        g_k[kidx + d1] = k1*c1 + k0*s1;
        g_v[kidx + d0] = v0;
        g_v[kidx + d1] = v1;

        size_t qidx = (size_t)token * NC + h*NDH;
        float q0v = qbuf[qidx + d0], q1v = qbuf[qidx + d1];
        qbuf[qidx + d0] = q0v*c0 - q1v*s0;
        qbuf[qidx + d1] = q1v*c1 + q0v*s1;
    }
}

// ---------------- flash attention (causal, fp32) ----------------
__global__ void __launch_bounds__(256) flash_kernel()
{
    int qt = blockIdx.x, bh = blockIdx.y;
    int b = bh >> 4, h = bh & 15;
    int q0 = qt * 64;
    const float* qp = g_q + ((size_t)(b*NT) + q0) * NC + h*NDH;
    const float* kp = g_k + (size_t)bh * NT * NDH;
    const float* vp = g_v + (size_t)bh * NT * NDH;

    __shared__ float Qs[64][65];
    __shared__ float Ks[64][33];
    __shared__ float Vs[32][65];
    __shared__ float Ps[32][65];

    int tid = threadIdx.x;
    int tx = tid & 15, ty = tid >> 4;

    for (int e = tid; e < 64*64; e += 256) {
        int d = e & 63, r = e >> 6;
        Qs[d][r] = qp[(size_t)r * NC + d];
    }

    float O[4][4];
    float m[4], l[4];
    #pragma unroll
    for (int i = 0; i < 4; i++) {
        m[i] = -1e30f; l[i] = 0.f;
        #pragma unroll
        for (int j = 0; j < 4; j++) O[i][j] = 0.f;
    }
    const float scale = 0.125f;
    int nkt = 2*qt + 2;

    for (int kt = 0; kt < nkt; kt++) {
        __syncthreads();
        int kbase = kt * 32;
        for (int e = tid; e < 32*64; e += 256) {
            int d = e & 63, c = e >> 6;
            Ks[d][c] = kp[(size_t)(kbase + c) * NDH + d];
            Vs[c][d] = vp[(size_t)(kbase + c) * NDH + d];
        }
        __syncthreads();

        float s[4][2];
        #pragma unroll
        for (int i = 0; i < 4; i++) { s[i][0] = 0.f; s[i][1] = 0.f; }
        #pragma unroll 8
        for (int d = 0; d < 64; d++) {
            float ar[4], br[2];
            #pragma unroll
            for (int i = 0; i < 4; i++) ar[i] = Qs[d][4*ty + i];
            br[0] = Ks[d][2*tx]; br[1] = Ks[d][2*tx + 1];
            #pragma unroll
            for (int i = 0; i < 4; i++) { s[i][0] += ar[i]*br[0]; s[i][1] += ar[i]*br[1]; }
        }
        bool need_mask = (kbase + 31 > q0);
        #pragma unroll
        for (int i = 0; i < 4; i++)
            #pragma unroll
            for (int j = 0; j < 2; j++) {
                s[i][j] *= scale;
                if (need_mask && (kbase + 2*tx + j > q0 + 4*ty + i)) s[i][j] = -1e30f;
            }
        float mt[4];
        #pragma unroll
        for (int i = 0; i < 4; i++) mt[i] = fmaxf(s[i][0], s[i][1]);
        #pragma unroll
        for (int o = 8; o; o >>= 1)
            #pragma unroll
            for (int i = 0; i < 4; i++)
                mt[i] = fmaxf(mt[i], __shfl_xor_sync(0xffffffffu, mt[i], o));

        float p[4][2], rs[4], sc[4];
        #pragma unroll
        for (int i = 0; i < 4; i++) {
            float mn = fmaxf(m[i], mt[i]);
            sc[i] = expf(m[i] - mn);
            m[i] = mn;
            p[i][0] = expf(s[i][0] - mn);
            p[i][1] = expf(s[i][1] - mn);
            rs[i] = p[i][0] + p[i][1];
        }
        #pragma unroll
        for (int o = 8; o; o >>= 1)
            #pragma unroll
            for (int i = 0; i < 4; i++)
                rs[i] += __shfl_xor_sync(0xffffffffu, rs[i], o);
        #pragma unroll
        for (int i = 0; i < 4; i++) {
            l[i] = l[i]*sc[i] + rs[i];
            #pragma unroll
            for (int j = 0; j < 4; j++) O[i][j] *= sc[i];
        }
        #pragma unroll
        for (int i = 0; i < 4; i++) {
            Ps[2*tx + 0][4*ty + i] = p[i][0];
            Ps[2*tx + 1][4*ty + i] = p[i][1];
        }
        __syncthreads();
        #pragma unroll 8
        for (int c = 0; c < 32; c++) {
            float ar[4], br[4];
            #pragma unroll
            for (int i = 0; i < 4; i++) ar[i] = Ps[c][4*ty + i];
            #pragma unroll
            for (int j = 0; j < 4; j++) br[j] = Vs[c][4*tx + j];
            #pragma unroll
            for (int i = 0; i < 4; i++)
                #pragma unroll
                for (int j = 0; j < 4; j++) O[i][j] += ar[i]*br[j];
        }
    }
    float* yp = g_y + ((size_t)(b*NT) + q0) * NC + h*NDH;
    #pragma unroll
    for (int i = 0; i < 4; i++) {
        float inv = 1.f / l[i];
        #pragma unroll
        for (int j = 0; j < 4; j++)
            yp[(size_t)(4*ty + i) * NC + 4*tx + j] = O[i][j] * inv;
    }
}

// ---------------- MoE routing ----------------
__global__ void route_kernel(const float* __restrict__ gate_w)
{
    __shared__ float s_frac[NE];
    __shared__ int   s_cnt[NE];
    if (threadIdx.x < NE) { s_frac[threadIdx.x] = 0.f; s_cnt[threadIdx.x] = 0; }
    __syncthreads();
    int warp = threadIdx.x >> 5, lane = threadIdx.x & 31;
    int token = blockIdx.x * 8 + warp;
    const float* xr = g_h2 + (size_t)token * NC;
    float acc[NE];
    #pragma unroll
    for (int e = 0; e < NE; e++) acc[e] = 0.f;
    for (int c = lane; c < NC; c += 32) {
        float v = xr[c];
        #pragma unroll
        for (int e = 0; e < NE; e++) acc[e] += v * gate_w[c*NE + e];
    }
    #pragma unroll
    for (int o = 16; o; o >>= 1)
        #pragma unroll
        for (int e = 0; e < NE; e++)
            acc[e] += __shfl_xor_sync(0xffffffffu, acc[e], o);
    if (lane == 0) {
        int i0 = 0;
        #pragma unroll
        for (int e = 1; e < NE; e++) if (acc[e] > acc[i0]) i0 = e;
        int i1 = (i0 == 0) ? 1 : 0;
        #pragma unroll
        for (int e = 0; e < NE; e++) if (e != i0 && acc[e] > acc[i1]) i1 = e;
        float ex = expf(acc[i1] - acc[i0]);
        float w0 = 1.f/(1.f + ex), w1 = ex/(1.f + ex);
        g_topi[token*2]     = i0; g_topi[token*2 + 1] = i1;
        g_topw[token*2]     = w0; g_topw[token*2 + 1] = w1;
        atomicAdd(&s_cnt[i0], 1); atomicAdd(&s_cnt[i1], 1);
        float mx = acc[0];
        #pragma unroll
        for (int e = 1; e < NE; e++) mx = fmaxf(mx, acc[e]);
        float den = 0.f, pe[NE];
        #pragma unroll
        for (int e = 0; e < NE; e++) { pe[e] = expf(acc[e] - mx); den += pe[e]; }
        float inv = 1.f/den;
        #pragma unroll
        for (int e = 0; e < NE; e++) atomicAdd(&s_frac[e], pe[e]*inv);
    }
    __syncthreads();
    if (threadIdx.x < NE) {
        atomicAdd(&g_frac[threadIdx.x], s_frac[threadIdx.x]);
        atomicAdd(&g_cnt [threadIdx.x], s_cnt [threadIdx.x]);
    }
}

__global__ void prefix_aux_kernel(float* __restrict__ aux)
{
    if (threadIdx.x == 0) {
        int off = 0;
        for (int e = 0; e < NE; e++) { g_off[e] = off; off += g_cnt[e]; }
        float s = 0.f;
        for (int e = 0; e < NE; e++) { float f = g_frac[e] * (1.f/NTOK); s += f*f; }
        *aux = 0.01f * 8.f * s;
    }
}

__global__ void scatter_kernel()
{
    int token = blockIdx.x * blockDim.x + threadIdx.x;
    if (token >= NTOK) return;
    #pragma unroll
    for (int j = 0; j < 2; j++) {
        int e   = g_topi[token*2 + j];
        float w = g_topw[token*2 + j];
        int slot = g_off[e] + atomicAdd(&g_pos[e], 1);
        g_tok[slot] = token; g_tw[slot] = w;
    }
}

// ---------------- launch ----------------
extern "C" void kernel_launch(void* const* d_in, const int* in_sizes, int n_in,
                              void* d_out, int out_size)
{
    const float* x      = (const float*)d_in[0];
    const float* ln1_w  = (const float*)d_in[1];
    const float* q_w    = (const float*)d_in[2];
    const float* k_w    = (const float*)d_in[3];
    const float* v_w    = (const float*)d_in[4];
    const float* k_up   = (const float*)d_in[5];
    const float* v_up   = (const float*)d_in[6];
    const float* c_w    = (const float*)d_in[7];
    const float* ln2_w  = (const float*)d_in[8];
    const float* gate_w = (const float*)d_in[9];
    const float* fc_w   = (const float*)d_in[10];
    const float* proj_w = (const float*)d_in[11];

    float* out  = (float*)d_out;
    float* klat = out + OFF_KL;
    float* vlat = out + OFF_VL;
    float* aux  = out + OFF_AUX;

    float *p_h, *p_q, *p_y, *p_h2;
    cudaGetSymbolAddress((void**)&p_h,  g_h);
    cudaGetSymbolAddress((void**)&p_q,  g_q);
    cudaGetSymbolAddress((void**)&p_y,  g_y);
    cudaGetSymbolAddress((void**)&p_h2, g_h2);

    init_kernel<<<1, 32>>>();
    ln_kernel<<<NTOK, 256>>>(x, ln1_w, p_h);

    gemm128<<<dim3( 8, 32), 256>>>(p_h, q_w, p_q, nullptr, 1024, 1024);
    gemm128<<<dim3( 4, 32), 256>>>(p_h, k_w, klat, nullptr,  512, 1024);
    gemm128<<<dim3( 4, 32), 256>>>(p_h, v_w, vlat, nullptr,  512, 1024);

    uprope_kernel<<<NTOK, 256>>>(klat, vlat, k_up, v_up, p_q);
    flash_kernel<<<dim3(16, NBH), 256>>>();

    gemm128<<<dim3( 8, 32), 256>>>(p_y, c_w, out, x, 1024, 1024);  // x1 = x + y@c_w
    ln_kernel<<<NTOK, 256>>>(out, ln2_w, p_h2);

    route_kernel<<<NTOK/8, 256>>>(gate_w);
    prefix_aux_kernel<<<1, 32>>>(aux);
    scatter_kernel<<<16, 256>>>();

    moe_gemm1<<<dim3(32, 32, NE), 256>>>(fc_w);
    moe_gemm2<<<dim3( 8, 32, NE), 256>>>(proj_w, out);
}

// round 5
// speedup vs baseline: 1.8300x; 1.8300x over previous
#include <cuda_runtime.h>
#include <math.h>
#include <stdint.h>

// ---------------- problem constants ----------------
#define NB   4
#define NT   1024
#define NC   1024
#define NH   16
#define NDH  64
#define NDL  32
#define NE   8
#define NDFF 4096
#define NTOK (NB*NT)     // 4096 tokens
#define NBH  (NB*NH)     // 64 (b,h) pairs

// output layout: [x | k_lat | v_lat | aux]
#define OFF_KL  ((size_t)NTOK*NC)
#define OFF_VL  (OFF_KL + (size_t)NTOK*NH*NDL)
#define OFF_AUX (OFF_VL + (size_t)NTOK*NH*NDL)

// ---------------- device scratch (no allocations allowed) ----------------
__device__ float g_h  [NTOK*NC];
__device__ float g_q  [NTOK*NC];
__device__ float g_k  [NBH*NT*NDH];
__device__ float g_v  [NBH*NT*NDH];
__device__ float g_y  [NTOK*NC];
__device__ float g_h2 [NTOK*NC];
__device__ float g_act[(size_t)NTOK*2*NDFF];
__device__ int   g_cnt[NE];
__device__ int   g_off[NE];
__device__ int   g_pos[NE];
__device__ int   g_topi[NTOK*2];
__device__ float g_topw[NTOK*2];
__device__ int   g_tok[NTOK*2];
__device__ float g_tw [NTOK*2];
__device__ float g_frac[NE];

__global__ void init_kernel() {
    int t = threadIdx.x;
    if (t < NE) { g_cnt[t] = 0; g_pos[t] = 0; g_frac[t] = 0.f; }
}

// ---------------- layernorm ----------------
__global__ void ln_kernel(const float* __restrict__ x, const float* __restrict__ w,
                          float* __restrict__ out) {
    int token = blockIdx.x;
    const float* xr = x + (size_t)token * NC;
    float s = 0.f, s2 = 0.f;
    for (int c = threadIdx.x; c < NC; c += 256) { float v = xr[c]; s += v; s2 += v*v; }
    #pragma unroll
    for (int o = 16; o; o >>= 1) {
        s  += __shfl_xor_sync(0xffffffffu, s,  o);
        s2 += __shfl_xor_sync(0xffffffffu, s2, o);
    }
    __shared__ float sw[8], sw2[8];
    __shared__ float s_mu, s_rstd;
    int warp = threadIdx.x >> 5, lane = threadIdx.x & 31;
    if (lane == 0) { sw[warp] = s; sw2[warp] = s2; }
    __syncthreads();
    if (threadIdx.x == 0) {
        float a = 0.f, b = 0.f;
        #pragma unroll
        for (int i = 0; i < 8; i++) { a += sw[i]; b += sw2[i]; }
        float mu  = a * (1.f/NC);
        float var = b * (1.f/NC) - mu*mu;
        s_mu = mu; s_rstd = rsqrtf(var + 1e-5f);
    }
    __syncthreads();
    float mu = s_mu, rstd = s_rstd;
    float* orow = out + (size_t)token * NC;
    for (int c = threadIdx.x; c < NC; c += 256)
        orow[c] = (xr[c] - mu) * rstd * w[c];
}

// ================= TF32 tensor-core GEMM (mma.sync.m16n8k8) ================
// CTA tile 128x128, K-tile 16, double-buffered. 8 warps in 2x4 -> warp tile
// 64x32 = 4x4 fragments of m16n8k8. tf32 conversion at SMEM store.
// As[k][m], Bs[k][n], padded to 136 words: fragment LDS bank = 8*(l&3)+(l>>2),
// all 32 distinct -> conflict-free.

__device__ __forceinline__ uint32_t f2tf32(float f) {
    uint32_t r; asm("cvt.rna.tf32.f32 %0, %1;" : "=r"(r) : "f"(f)); return r;
}

__device__ __forceinline__ void mma_tf32(float4& d, const uint32_t* a, const uint32_t* b) {
    asm volatile("mma.sync.aligned.m16n8k8.row.col.f32.tf32.tf32.f32 "
        "{%0,%1,%2,%3}, {%4,%5,%6,%7}, {%8,%9}, {%0,%1,%2,%3};"
        : "+f"(d.x), "+f"(d.y), "+f"(d.z), "+f"(d.w)
        : "r"(a[0]), "r"(a[1]), "r"(a[2]), "r"(a[3]), "r"(b[0]), "r"(b[1]));
}

#define TC_PROLOGUE() \
    __shared__ __align__(16) uint32_t As[2][16][136]; \
    __shared__ __align__(16) uint32_t Bs[2][16][136]; \
    int tid = threadIdx.x; \
    int lane = tid & 31, wid = tid >> 5; \
    int qid = lane >> 2, tq = lane & 3; \
    int wm0 = (wid & 1) * 64, wn0 = (wid >> 1) * 32; \
    int am = tid >> 1, ak = (tid & 1) * 8; \
    int bk = tid >> 4, bn = (tid & 15) * 8; \
    float4 acc[4][4]; \
    _Pragma("unroll") \
    for (int i = 0; i < 4; i++) \
        _Pragma("unroll") \
        for (int j = 0; j < 4; j++) acc[i][j] = make_float4(0.f,0.f,0.f,0.f);

#define TC_STORE_TILE(buf) \
    _Pragma("unroll") \
    for (int i = 0; i < 4; i++) { \
        As[buf][ak+i  ][am] = f2tf32(((const float*)&a4a)[i]); \
        As[buf][ak+4+i][am] = f2tf32(((const float*)&a4b)[i]); \
        ((uint32_t*)&Bs[buf][bk][bn])[i]   = f2tf32(((const float*)&b4a)[i]); \
        ((uint32_t*)&Bs[buf][bk][bn])[4+i] = f2tf32(((const float*)&b4b)[i]); \
    }

#define TC_COMPUTE(buf) \
    _Pragma("unroll") \
    for (int ks = 0; ks < 2; ks++) { \
        int kk = ks * 8; \
        uint32_t af[4][4], bf[4][2]; \
        _Pragma("unroll") \
        for (int mf = 0; mf < 4; mf++) { \
            int m = wm0 + mf*16 + qid; \
            af[mf][0] = As[buf][kk + tq    ][m]; \
            af[mf][1] = As[buf][kk + tq    ][m + 8]; \
            af[mf][2] = As[buf][kk + 4 + tq][m]; \
            af[mf][3] = As[buf][kk + 4 + tq][m + 8]; \
        } \
        _Pragma("unroll") \
        for (int nf = 0; nf < 4; nf++) { \
            int n = wn0 + nf*8 + qid; \
            bf[nf][0] = Bs[buf][kk + tq    ][n]; \
            bf[nf][1] = Bs[buf][kk + 4 + tq][n]; \
        } \
        _Pragma("unroll") \
        for (int mf = 0; mf < 4; mf++) \
            _Pragma("unroll") \
            for (int nf = 0; nf < 4; nf++) \
                mma_tf32(acc[mf][nf], af[mf], bf[nf]); \
    }

#define TC_MAINLOOP(NTILES, LDA_STRIDE, LDB_STRIDE) \
    float4 a4a = *(const float4*)(Aptr); \
    float4 a4b = *(const float4*)(Aptr + 4); \
    float4 b4a = *(const float4*)(Bptr); \
    float4 b4b = *(const float4*)(Bptr + 4); \
    TC_STORE_TILE(0); \
    __syncthreads(); \
    for (int kt = 0; kt < (NTILES); kt++) { \
        int cur = kt & 1, nxt = cur ^ 1; \
        if (kt + 1 < (NTILES)) { \
            a4a = *(const float4*)(Aptr + (size_t)(kt+1)*16); \
            a4b = *(const float4*)(Aptr + (size_t)(kt+1)*16 + 4); \
            b4a = *(const float4*)(Bptr + (size_t)(kt+1)*16*(LDB_STRIDE)); \
            b4b = *(const float4*)(Bptr + (size_t)(kt+1)*16*(LDB_STRIDE) + 4); \
        } \
        TC_COMPUTE(cur); \
        if (kt + 1 < (NTILES)) { \
            TC_STORE_TILE(nxt); \
            __syncthreads(); \
        } \
    }

// ---- plain: C[M,N] = A[M,K] @ B[K,N] (+resid). M,N multiples of 128 -------
__global__ void __launch_bounds__(256) gemm128(
    const float* __restrict__ A, const float* __restrict__ Bm,
    float* __restrict__ Cm, const float* __restrict__ resid, int N, int K)
{
    TC_PROLOGUE();
    int row0 = blockIdx.y * 128, col0 = blockIdx.x * 128;
    const float* Aptr = A  + (size_t)(row0 + am) * K + ak;
    const float* Bptr = Bm + (size_t)bk * N + col0 + bn;
    int ntiles = K >> 4;
    TC_MAINLOOP(ntiles, K, N);

    #pragma unroll
    for (int mf = 0; mf < 4; mf++) {
        int r0 = row0 + wm0 + mf*16 + qid;
        #pragma unroll
        for (int nf = 0; nf < 4; nf++) {
            int c = col0 + wn0 + nf*8 + 2*tq;
            float4 v = acc[mf][nf];
            size_t o0 = (size_t)r0 * N + c;
            size_t o1 = (size_t)(r0 + 8) * N + c;
            float2 p0 = make_float2(v.x, v.y);
            float2 p1 = make_float2(v.z, v.w);
            if (resid) {
                float2 q0 = *(const float2*)(resid + o0);
                float2 q1 = *(const float2*)(resid + o1);
                p0.x += q0.x; p0.y += q0.y; p1.x += q1.x; p1.y += q1.y;
            }
            *(float2*)(Cm + o0) = p0;
            *(float2*)(Cm + o1) = p1;
        }
    }
}

// ---- MoE GEMM1: act = gelu(h2[gather] @ fc_w[e]); grid (32, 32, 8) --------
__global__ void __launch_bounds__(256) moe_gemm1(const float* __restrict__ FC)
{
    int e = blockIdx.z;
    int Me = g_cnt[e]; if (Me == 0) return;
    int base = g_off[e];
    int row0 = blockIdx.y * 128; if (row0 >= Me) return;
    int col0 = blockIdx.x * 128;
    const float* Bm = FC + (size_t)e * NC * NDFF;

    TC_PROLOGUE();
    int ar_ = row0 + am;
    int atok = (ar_ < Me) ? g_tok[base + ar_] : g_tok[base];
    const float* Aptr = g_h2 + (size_t)atok * NC + ak;
    const float* Bptr = Bm + (size_t)bk * NDFF + col0 + bn;
    TC_MAINLOOP(NC >> 4, NC, NDFF);

    #pragma unroll
    for (int mf = 0; mf < 4; mf++) {
        #pragma unroll
        for (int rr = 0; rr < 2; rr++) {
            int r = row0 + wm0 + mf*16 + qid + rr*8;
            if (r < Me) {
                float* orow = g_act + (size_t)(base + r) * NDFF + col0;
                #pragma unroll
                for (int nf = 0; nf < 4; nf++) {
                    int c = wn0 + nf*8 + 2*tq;
                    float v0 = rr ? acc[mf][nf].z : acc[mf][nf].x;
                    float v1 = rr ? acc[mf][nf].w : acc[mf][nf].y;
                    float2 g;
                    g.x = 0.5f * v0 * (1.f + erff(v0 * 0.70710678118654752f));
                    g.y = 0.5f * v1 * (1.f + erff(v1 * 0.70710678118654752f));
                    *(float2*)(orow + c) = g;
                }
            }
        }
    }
}

// ---- MoE GEMM2: xout[tok] += w*(act @ proj_w[e]); grid (8, 32, 8) ---------
__global__ void __launch_bounds__(256) moe_gemm2(const float* __restrict__ PW,
                                                 float* __restrict__ xout)
{
    int e = blockIdx.z;
    int Me = g_cnt[e]; if (Me == 0) return;
    int base = g_off[e];
    int row0 = blockIdx.y * 128; if (row0 >= Me) return;
    int col0 = blockIdx.x * 128;
    const float* Bm = PW + (size_t)e * NDFF * NC;

    TC_PROLOGUE();
    int ar_ = row0 + am;
    int aslot = base + ((ar_ < Me) ? ar_ : (Me - 1));
    const float* Aptr = g_act + (size_t)aslot * NDFF + ak;
    const float* Bptr = Bm + (size_t)bk * NC + col0 + bn;
    TC_MAINLOOP(NDFF >> 4, NDFF, NC);

    #pragma unroll
    for (int mf = 0; mf < 4; mf++) {
        #pragma unroll
        for (int rr = 0; rr < 2; rr++) {
            int r = row0 + wm0 + mf*16 + qid + rr*8;
            if (r < Me) {
                int tok = g_tok[base + r];
                float w = g_tw[base + r];
                size_t off = (size_t)tok * NC + col0;
                #pragma unroll
                for (int nf = 0; nf < 4; nf++) {
                    int c = wn0 + nf*8 + 2*tq;
                    float v0 = rr ? acc[mf][nf].z : acc[mf][nf].x;
                    float v1 = rr ? acc[mf][nf].w : acc[mf][nf].y;
                    atomicAdd(&xout[off + c],     w * v0);
                    atomicAdd(&xout[off + c + 1], w * v1);
                }
            }
        }
    }
}

// ---------------- latent->head up-projection + RoPE ----------------
__global__ void uprope_kernel(const float* __restrict__ klat, const float* __restrict__ vlat,
                              const float* __restrict__ kup,  const float* __restrict__ vup,
                              float* __restrict__ qbuf)
{
    int token = blockIdx.x;
    int b = token >> 10, t = token & 1023;
    __shared__ float skl[NH*NDL], svl[NH*NDL];
    __shared__ float sku[NDL*NDH], svu[NDL*NDH];
    int tid = threadIdx.x;
    for (int e = tid; e < NH*NDL; e += 256) {
        skl[e] = klat[(size_t)token*NH*NDL + e];
        svl[e] = vlat[(size_t)token*NH*NDL + e];
    }
    for (int e = tid; e < NDL*NDH; e += 256) { sku[e] = kup[e]; svu[e] = vup[e]; }
    __syncthreads();

    for (int p = tid; p < NH*32; p += 256) {
        int h = p >> 5, i = p & 31;
        int d0 = 2*i, d1 = 2*i + 1;
        float k0 = 0.f, k1 = 0.f, v0 = 0.f, v1 = 0.f;
        #pragma unroll
        for (int l = 0; l < NDL; l++) {
            float kl = skl[h*NDL + l], vl = svl[h*NDL + l];
            k0 += kl * sku[l*NDH + d0]; k1 += kl * sku[l*NDH + d1];
            v0 += vl * svu[l*NDH + d0]; v1 += vl * svu[l*NDH + d1];
        }
        int j0 = (d0 < 32) ? d0 : d0 - 32;
        int j1 = (d1 < 32) ? d1 : d1 - 32;
        float a0 = (float)t * powf(10000.f, -(float)j0 * (1.f/32.f));
        float a1 = (float)t * powf(10000.f, -(float)j1 * (1.f/32.f));
        float c0 = cosf(a0), s0 = sinf(a0), c1 = cosf(a1), s1 = sinf(a1);

        size_t kidx = ((size_t)(b*NH + h) * NT + t) * NDH;
        g_k[kidx + d0] = k0*c0 - k1*s0;
        g_k[kidx + d1] = k1*c1 + k0*s1;
        g_v[kidx + d0] = v0;
        g_v[kidx + d1] = v1;

        size_t qidx = (size_t)token * NC + h*NDH;
        float q0v = qbuf[qidx + d0], q1v = qbuf[qidx + d1];
        qbuf[qidx + d0] = q0v*c0 - q1v*s0;
        qbuf[qidx + d1] = q1v*c1 + q0v*s1;
    }
}

// ---------------- flash attention (causal, fp32) ----------------
__global__ void __launch_bounds__(256) flash_kernel()
{
    int qt = blockIdx.x, bh = blockIdx.y;
    int b = bh >> 4, h = bh & 15;
    int q0 = qt * 64;
    const float* qp = g_q + ((size_t)(b*NT) + q0) * NC + h*NDH;
    const float* kp = g_k + (size_t)bh * NT * NDH;
    const float* vp = g_v + (size_t)bh * NT * NDH;

    __shared__ float Qs[64][65];
    __shared__ float Ks[64][33];
    __shared__ float Vs[32][65];
    __shared__ float Ps[32][65];

    int tid = threadIdx.x;
    int tx = tid & 15, ty = tid >> 4;

    for (int e = tid; e < 64*64; e += 256) {
        int d = e & 63, r = e >> 6;
        Qs[d][r] = qp[(size_t)r * NC + d];
    }

    float O[4][4];
    float m[4], l[4];
    #pragma unroll
    for (int i = 0; i < 4; i++) {
        m[i] = -1e30f; l[i] = 0.f;
        #pragma unroll
        for (int j = 0; j < 4; j++) O[i][j] = 0.f;
    }
    const float scale = 0.125f;
    int nkt = 2*qt + 2;

    for (int kt = 0; kt < nkt; kt++) {
        __syncthreads();
        int kbase = kt * 32;
        for (int e = tid; e < 32*64; e += 256) {
            int d = e & 63, c = e >> 6;
            Ks[d][c] = kp[(size_t)(kbase + c) * NDH + d];
            Vs[c][d] = vp[(size_t)(kbase + c) * NDH + d];
        }
        __syncthreads();

        float s[4][2];
        #pragma unroll
        for (int i = 0; i < 4; i++) { s[i][0] = 0.f; s[i][1] = 0.f; }
        #pragma unroll 8
        for (int d = 0; d < 64; d++) {
            float ar[4], br[2];
            #pragma unroll
            for (int i = 0; i < 4; i++) ar[i] = Qs[d][4*ty + i];
            br[0] = Ks[d][2*tx]; br[1] = Ks[d][2*tx + 1];
            #pragma unroll
            for (int i = 0; i < 4; i++) { s[i][0] += ar[i]*br[0]; s[i][1] += ar[i]*br[1]; }
        }
        bool need_mask = (kbase + 31 > q0);
        #pragma unroll
        for (int i = 0; i < 4; i++)
            #pragma unroll
            for (int j = 0; j < 2; j++) {
                s[i][j] *= scale;
                if (need_mask && (kbase + 2*tx + j > q0 + 4*ty + i)) s[i][j] = -1e30f;
            }
        float mt[4];
        #pragma unroll
        for (int i = 0; i < 4; i++) mt[i] = fmaxf(s[i][0], s[i][1]);
        #pragma unroll
        for (int o = 8; o; o >>= 1)
            #pragma unroll
            for (int i = 0; i < 4; i++)
                mt[i] = fmaxf(mt[i], __shfl_xor_sync(0xffffffffu, mt[i], o));

        float p[4][2], rs[4], sc[4];
        #pragma unroll
        for (int i = 0; i < 4; i++) {
            float mn = fmaxf(m[i], mt[i]);
            sc[i] = expf(m[i] - mn);
            m[i] = mn;
            p[i][0] = expf(s[i][0] - mn);
            p[i][1] = expf(s[i][1] - mn);
            rs[i] = p[i][0] + p[i][1];
        }
        #pragma unroll
        for (int o = 8; o; o >>= 1)
            #pragma unroll
            for (int i = 0; i < 4; i++)
                rs[i] += __shfl_xor_sync(0xffffffffu, rs[i], o);
        #pragma unroll
        for (int i = 0; i < 4; i++) {
            l[i] = l[i]*sc[i] + rs[i];
            #pragma unroll
            for (int j = 0; j < 4; j++) O[i][j] *= sc[i];
        }
        #pragma unroll
        for (int i = 0; i < 4; i++) {
            Ps[2*tx + 0][4*ty + i] = p[i][0];
            Ps[2*tx + 1][4*ty + i] = p[i][1];
        }
        __syncthreads();
        #pragma unroll 8
        for (int c = 0; c < 32; c++) {
            float ar[4], br[4];
            #pragma unroll
            for (int i = 0; i < 4; i++) ar[i] = Ps[c][4*ty + i];
            #pragma unroll
            for (int j = 0; j < 4; j++) br[j] = Vs[c][4*tx + j];
            #pragma unroll
            for (int i = 0; i < 4; i++)
                #pragma unroll
                for (int j = 0; j < 4; j++) O[i][j] += ar[i]*br[j];
        }
    }
    float* yp = g_y + ((size_t)(b*NT) + q0) * NC + h*NDH;
    #pragma unroll
    for (int i = 0; i < 4; i++) {
        float inv = 1.f / l[i];
        #pragma unroll
        for (int j = 0; j < 4; j++)
            yp[(size_t)(4*ty + i) * NC + 4*tx + j] = O[i][j] * inv;
    }
}

// ---------------- MoE routing ----------------
__global__ void route_kernel(const float* __restrict__ gate_w)
{
    __shared__ float s_frac[NE];
    __shared__ int   s_cnt[NE];
    if (threadIdx.x < NE) { s_frac[threadIdx.x] = 0.f; s_cnt[threadIdx.x] = 0; }
    __syncthreads();
    int warp = threadIdx.x >> 5, lane = threadIdx.x & 31;
    int token = blockIdx.x * 8 + warp;
    const float* xr = g_h2 + (size_t)token * NC;
    float acc[NE];
    #pragma unroll
    for (int e = 0; e < NE; e++) acc[e] = 0.f;
    for (int c = lane; c < NC; c += 32) {
        float v = xr[c];
        #pragma unroll
        for (int e = 0; e < NE; e++) acc[e] += v * gate_w[c*NE + e];
    }
    #pragma unroll
    for (int o = 16; o; o >>= 1)
        #pragma unroll
        for (int e = 0; e < NE; e++)
            acc[e] += __shfl_xor_sync(0xffffffffu, acc[e], o);
    if (lane == 0) {
        int i0 = 0;
        #pragma unroll
        for (int e = 1; e < NE; e++) if (acc[e] > acc[i0]) i0 = e;
        int i1 = (i0 == 0) ? 1 : 0;
        #pragma unroll
        for (int e = 0; e < NE; e++) if (e != i0 && acc[e] > acc[i1]) i1 = e;
        float ex = expf(acc[i1] - acc[i0]);
        float w0 = 1.f/(1.f + ex), w1 = ex/(1.f + ex);
        g_topi[token*2]     = i0; g_topi[token*2 + 1] = i1;
        g_topw[token*2]     = w0; g_topw[token*2 + 1] = w1;
        atomicAdd(&s_cnt[i0], 1); atomicAdd(&s_cnt[i1], 1);
        float mx = acc[0];
        #pragma unroll
        for (int e = 1; e < NE; e++) mx = fmaxf(mx, acc[e]);
        float den = 0.f, pe[NE];
        #pragma unroll
        for (int e = 0; e < NE; e++) { pe[e] = expf(acc[e] - mx); den += pe[e]; }
        float inv = 1.f/den;
        #pragma unroll
        for (int e = 0; e < NE; e++) atomicAdd(&s_frac[e], pe[e]*inv);
    }
    __syncthreads();
    if (threadIdx.x < NE) {
        atomicAdd(&g_frac[threadIdx.x], s_frac[threadIdx.x]);
        atomicAdd(&g_cnt [threadIdx.x], s_cnt [threadIdx.x]);
    }
}

__global__ void prefix_aux_kernel(float* __restrict__ aux)
{
    if (threadIdx.x == 0) {
        int off = 0;
        for (int e = 0; e < NE; e++) { g_off[e] = off; off += g_cnt[e]; }
        float s = 0.f;
        for (int e = 0; e < NE; e++) { float f = g_frac[e] * (1.f/NTOK); s += f*f; }
        *aux = 0.01f * 8.f * s;
    }
}

__global__ void scatter_kernel()
{
    int token = blockIdx.x * blockDim.x + threadIdx.x;
    if (token >= NTOK) return;
    #pragma unroll
    for (int j = 0; j < 2; j++) {
        int e   = g_topi[token*2 + j];
        float w = g_topw[token*2 + j];
        int slot = g_off[e] + atomicAdd(&g_pos[e], 1);
        g_tok[slot] = token; g_tw[slot] = w;
    }
}

// ---------------- launch ----------------
extern "C" void kernel_launch(void* const* d_in, const int* in_sizes, int n_in,
                              void* d_out, int out_size)
{
    const float* x      = (const float*)d_in[0];
    const float* ln1_w  = (const float*)d_in[1];
    const float* q_w    = (const float*)d_in[2];
    const float* k_w    = (const float*)d_in[3];
    const float* v_w    = (const float*)d_in[4];
    const float* k_up   = (const float*)d_in[5];
    const float* v_up   = (const float*)d_in[6];
    const float* c_w    = (const float*)d_in[7];
    const float* ln2_w  = (const float*)d_in[8];
    const float* gate_w = (const float*)d_in[9];
    const float* fc_w   = (const float*)d_in[10];
    const float* proj_w = (const float*)d_in[11];

    float* out  = (float*)d_out;
    float* klat = out + OFF_KL;
    float* vlat = out + OFF_VL;
    float* aux  = out + OFF_AUX;

    float *p_h, *p_q, *p_y, *p_h2;
    cudaGetSymbolAddress((void**)&p_h,  g_h);
    cudaGetSymbolAddress((void**)&p_q,  g_q);
    cudaGetSymbolAddress((void**)&p_y,  g_y);
    cudaGetSymbolAddress((void**)&p_h2, g_h2);

    init_kernel<<<1, 32>>>();
    ln_kernel<<<NTOK, 256>>>(x, ln1_w, p_h);

    gemm128<<<dim3( 8, 32), 256>>>(p_h, q_w, p_q, nullptr, 1024, 1024);
    gemm128<<<dim3( 4, 32), 256>>>(p_h, k_w, klat, nullptr,  512, 1024);
    gemm128<<<dim3( 4, 32), 256>>>(p_h, v_w, vlat, nullptr,  512, 1024);

    uprope_kernel<<<NTOK, 256>>>(klat, vlat, k_up, v_up, p_q);
    flash_kernel<<<dim3(16, NBH), 256>>>();

    gemm128<<<dim3( 8, 32), 256>>>(p_y, c_w, out, x, 1024, 1024);  // x1 = x + y@c_w
    ln_kernel<<<NTOK, 256>>>(out, ln2_w, p_h2);

    route_kernel<<<NTOK/8, 256>>>(gate_w);
    prefix_aux_kernel<<<1, 32>>>(aux);
    scatter_kernel<<<16, 256>>>();

    moe_gemm1<<<dim3(32, 32, NE), 256>>>(fc_w);
    moe_gemm2<<<dim3( 8, 32, NE), 256>>>(proj_w, out);
}